// round 11
// baseline (speedup 1.0000x reference)
#include <cuda_runtime.h>
#include <math.h>
#include <stdint.h>

// ---------------- problem constants ----------------
#define HH 64
#define PP 64
#define NN 128
#define GG 8
#define KK 4
#define DM 4096
#define II 4096           // H*P
#define GN 1024           // G*N
#define CONVD 6144        // I + 2*GN
#define PROJ 10304        // I + CONVD + H
#define LSEQ 2048
#define BB 2
#define BT 4096           // B*L
#define GRPSZ 512         // I/G

#define OUT_ELEMS (4096*4096)
#define CS_ELEMS  (BB*CONVD*(KK-1))

// ---------------- scratch (device globals; no allocs allowed) ----------------
static __device__ float g_proj[(size_t)BT * PROJ];
static __device__ float g_xbc[(size_t)BT * CONVD];
static __device__ float g_dtp[BT * HH];
static __device__ float g_dA[BT * HH];
static __device__ float g_y[(size_t)BT * II];
static __device__ float g_yn[(size_t)BT * II];
static __device__ float g_a32[(size_t)BT * DM];        // tf32-rounded A operand
static __device__ float g_w32[(size_t)PROJ * DM];      // tf32-rounded weights (reused)

__device__ __forceinline__ float silu_f(float x) {
    return x / (1.0f + __expf(-x));
}
__device__ __forceinline__ float softplus_f(float x) {
    return (x > 20.0f) ? x : log1pf(expf(x));
}
__device__ __forceinline__ float tf32_rna(float x) {
    uint32_t r;
    asm("cvt.rna.tf32.f32 %0, %1;" : "=r"(r) : "f"(x));
    return __uint_as_float(r);
}

// ---------------- tf32 rounding pass (RNA, zero-mean error) ----------------
__global__ void round_tf32_kernel(const float* __restrict__ src,
                                  float* __restrict__ dst, int n4) {
    int i = blockIdx.x * blockDim.x + threadIdx.x;
    if (i >= n4) return;
    float4 v = ((const float4*)src)[i];
    v.x = tf32_rna(v.x); v.y = tf32_rna(v.y);
    v.z = tf32_rna(v.z); v.w = tf32_rna(v.w);
    ((float4*)dst)[i] = v;
}

// ---------------- hybrid GEMM: C[M,N] = A[M,K] * B[N,K]^T ----------------
// Column tiles bx < NTB use the tensor-core tf32 path (R2 structure, proven);
// remaining tiles use the SIMT fp32 path (R1 structure, proven).
// Both: 128x128 CTA tile, 256 threads, 2 CTAs/SM -> tensor & fma pipes overlap
// when CTAs of both kinds co-reside on an SM.
__global__ __launch_bounds__(256, 2)
void gemm_hybrid_kernel(const float* __restrict__ A, const float* __restrict__ B,
                        float* __restrict__ C, int M, int N, int K, int NTB) {
    __shared__ __align__(16) float sm[10240];   // 40 KB, unioned per path

    const int tid  = threadIdx.x;
    const int bx   = blockIdx.x;
    const int row0 = blockIdx.y * 128;
    const int col0 = bx * 128;

    if (bx < NTB) {
        // ================= tensor-core tf32 path (R2) =================
        // layout: As[2][128][20] at sm, Bs[2][128][20] at sm+5120
        float* As = sm;
        float* Bs = sm + 5120;

        const int warp = tid >> 5, lane = tid & 31;
        const int g    = lane >> 2, tig = lane & 3;
        const int wm   = (warp >> 2) * 64;
        const int wn   = (warp & 3) * 32;

        const int lr = tid >> 1;
        const int lk = (tid & 1) * 8;
        const float* Ag = A + (size_t)(row0 + lr) * K + lk;
        const float* Bg = B + (size_t)(col0 + lr) * K + lk;
        const int bsz = ((col0 + lr) < N) ? 16 : 0;

        float acc[4][4][4];
#pragma unroll
        for (int mt = 0; mt < 4; mt++)
#pragma unroll
            for (int nt = 0; nt < 4; nt++)
#pragma unroll
                for (int i = 0; i < 4; i++) acc[mt][nt][i] = 0.f;

        auto load_tiles = [&](int buf, int kt) {
            uint32_t a_s = (uint32_t)__cvta_generic_to_shared(
                As + buf * 2560 + lr * 20 + lk);
            uint32_t b_s = (uint32_t)__cvta_generic_to_shared(
                Bs + buf * 2560 + lr * 20 + lk);
            const float* ap = Ag + kt;
            const float* bp = Bg + kt;
            asm volatile("cp.async.cg.shared.global [%0], [%1], 16;\n" :: "r"(a_s), "l"(ap));
            asm volatile("cp.async.cg.shared.global [%0], [%1], 16;\n" :: "r"(a_s + 16), "l"(ap + 4));
            asm volatile("cp.async.cg.shared.global [%0], [%1], 16, %2;\n" :: "r"(b_s), "l"(bp), "r"(bsz));
            asm volatile("cp.async.cg.shared.global [%0], [%1], 16, %2;\n" :: "r"(b_s + 16), "l"(bp + 4), "r"(bsz));
        };

        const int nk = K / 16;
        load_tiles(0, 0);
        asm volatile("cp.async.commit_group;\n");

        for (int it = 0; it < nk; it++) {
            asm volatile("cp.async.wait_group 0;\n");
            __syncthreads();
            if (it + 1 < nk) {
                load_tiles((it + 1) & 1, (it + 1) * 16);
                asm volatile("cp.async.commit_group;\n");
            }
            const float* Ab = As + (it & 1) * 2560;
            const float* Bb = Bs + (it & 1) * 2560;
#pragma unroll
            for (int ks = 0; ks < 2; ks++) {
                const int k0 = ks * 8;
                uint32_t af[4][4], bf[4][2];
#pragma unroll
                for (int mt = 0; mt < 4; mt++) {
                    int r = wm + mt * 16 + g;
                    af[mt][0] = __float_as_uint(Ab[r * 20 + k0 + tig]);
                    af[mt][1] = __float_as_uint(Ab[(r + 8) * 20 + k0 + tig]);
                    af[mt][2] = __float_as_uint(Ab[r * 20 + k0 + 4 + tig]);
                    af[mt][3] = __float_as_uint(Ab[(r + 8) * 20 + k0 + 4 + tig]);
                }
#pragma unroll
                for (int nt = 0; nt < 4; nt++) {
                    int cc = wn + nt * 8 + g;
                    bf[nt][0] = __float_as_uint(Bb[cc * 20 + k0 + tig]);
                    bf[nt][1] = __float_as_uint(Bb[cc * 20 + k0 + 4 + tig]);
                }
#pragma unroll
                for (int mt = 0; mt < 4; mt++)
#pragma unroll
                    for (int nt = 0; nt < 4; nt++)
                        asm volatile(
                            "mma.sync.aligned.m16n8k8.row.col.f32.tf32.tf32.f32 "
                            "{%0,%1,%2,%3}, {%4,%5,%6,%7}, {%8,%9}, {%0,%1,%2,%3};\n"
                            : "+f"(acc[mt][nt][0]), "+f"(acc[mt][nt][1]),
                              "+f"(acc[mt][nt][2]), "+f"(acc[mt][nt][3])
                            : "r"(af[mt][0]), "r"(af[mt][1]), "r"(af[mt][2]), "r"(af[mt][3]),
                              "r"(bf[nt][0]), "r"(bf[nt][1]));
            }
        }

#pragma unroll
        for (int mt = 0; mt < 4; mt++) {
            int r = row0 + wm + mt * 16 + g;
#pragma unroll
            for (int nt = 0; nt < 4; nt++) {
                int cc = col0 + wn + nt * 8 + 2 * tig;
                if (cc < N) {
                    float* p0 = C + (size_t)r * N + cc;
                    float* p1 = C + (size_t)(r + 8) * N + cc;
                    p0[0] = acc[mt][nt][0]; p0[1] = acc[mt][nt][1];
                    p1[0] = acc[mt][nt][2]; p1[1] = acc[mt][nt][3];
                }
            }
        }
    } else {
        // ================= SIMT fp32 path (R1) =================
        // layout: As[16][132] at sm, Bs[16][132] at sm+2112
        float* As = sm;
        float* Bs = sm + 2112;

        const int tx = tid & 15;
        const int ty = tid >> 4;

        const int lr = tid >> 1;
        const int lc = (tid & 1) * 8;

        const bool avalid = (row0 + lr) < M;
        const bool bvalid = (col0 + lr) < N;
        const float* Aptr = A + (size_t)(row0 + lr) * K + lc;
        const float* Bptr = B + (size_t)(col0 + lr) * K + lc;

        float4 pa0, pa1, pb0, pb1;
        auto fetch = [&](int kt) {
            if (avalid) {
                pa0 = *(const float4*)(Aptr + kt);
                pa1 = *(const float4*)(Aptr + kt + 4);
            } else {
                pa0 = make_float4(0.f,0.f,0.f,0.f); pa1 = pa0;
            }
            if (bvalid) {
                pb0 = *(const float4*)(Bptr + kt);
                pb1 = *(const float4*)(Bptr + kt + 4);
            } else {
                pb0 = make_float4(0.f,0.f,0.f,0.f); pb1 = pb0;
            }
        };

        float acc[8][8];
#pragma unroll
        for (int i = 0; i < 8; i++)
#pragma unroll
            for (int j = 0; j < 8; j++) acc[i][j] = 0.f;

        fetch(0);
        for (int kt = 0; kt < K; kt += 16) {
            __syncthreads();
            As[(lc+0)*132+lr] = pa0.x; As[(lc+1)*132+lr] = pa0.y;
            As[(lc+2)*132+lr] = pa0.z; As[(lc+3)*132+lr] = pa0.w;
            As[(lc+4)*132+lr] = pa1.x; As[(lc+5)*132+lr] = pa1.y;
            As[(lc+6)*132+lr] = pa1.z; As[(lc+7)*132+lr] = pa1.w;
            Bs[(lc+0)*132+lr] = pb0.x; Bs[(lc+1)*132+lr] = pb0.y;
            Bs[(lc+2)*132+lr] = pb0.z; Bs[(lc+3)*132+lr] = pb0.w;
            Bs[(lc+4)*132+lr] = pb1.x; Bs[(lc+5)*132+lr] = pb1.y;
            Bs[(lc+6)*132+lr] = pb1.z; Bs[(lc+7)*132+lr] = pb1.w;
            __syncthreads();
            if (kt + 16 < K) fetch(kt + 16);

#pragma unroll
            for (int k = 0; k < 16; k++) {
                float4 a0 = *(const float4*)&As[k*132 + ty * 8];
                float4 a1 = *(const float4*)&As[k*132 + ty * 8 + 4];
                float4 b0 = *(const float4*)&Bs[k*132 + tx * 8];
                float4 b1 = *(const float4*)&Bs[k*132 + tx * 8 + 4];
                float ra[8] = {a0.x, a0.y, a0.z, a0.w, a1.x, a1.y, a1.z, a1.w};
                float rb[8] = {b0.x, b0.y, b0.z, b0.w, b1.x, b1.y, b1.z, b1.w};
#pragma unroll
                for (int i = 0; i < 8; i++)
#pragma unroll
                    for (int j = 0; j < 8; j++)
                        acc[i][j] = fmaf(ra[i], rb[j], acc[i][j]);
            }
        }

#pragma unroll
        for (int i = 0; i < 8; i++) {
            int m = row0 + ty * 8 + i;
            if (m < M) {
#pragma unroll
                for (int j = 0; j < 8; j++) {
                    int n = col0 + tx * 8 + j;
                    if (n < N) C[(size_t)m * N + n] = acc[i][j];
                }
            }
        }
    }
}

// ---------------- conv1d (depthwise, K=4, causal) + silu; 4 outputs/thread ----------------
__global__ void conv_kernel(const float* __restrict__ cw,
                            const float* __restrict__ cb,
                            float* __restrict__ conv_state) {
    int idx = blockIdx.x * blockDim.x + threadIdx.x;   // over (BT/4)*CONVD
    if (idx >= (BT / 4) * CONVD) return;
    int lb = idx / CONVD;
    int c  = idx - lb * CONVD;
    int b  = lb >> 9;                   // 512 l-blocks per batch
    int l0 = (lb & 511) * 4;

    const float w0 = cw[c * 4 + 0], w1 = cw[c * 4 + 1], w2 = cw[c * 4 + 2], w3 = cw[c * 4 + 3];
    const float bias = cb[c];
    const size_t colbase = (size_t)II + c;
    const size_t rowbase = ((size_t)b * LSEQ + l0) * PROJ + colbase;

    float xv[7];
#pragma unroll
    for (int j = 0; j < 3; j++)
        xv[j] = (l0 - 3 + j >= 0) ? g_proj[rowbase + (size_t)(j - 3) * PROJ] : 0.f;
#pragma unroll
    for (int j = 3; j < 7; j++)
        xv[j] = g_proj[rowbase + (size_t)(j - 3) * PROJ];

    size_t obase = ((size_t)b * LSEQ + l0) * CONVD + c;
#pragma unroll
    for (int j = 0; j < 4; j++) {
        float v = bias + xv[j] * w0 + xv[j + 1] * w1 + xv[j + 2] * w2 + xv[j + 3] * w3;
        g_xbc[obase + (size_t)j * CONVD] = silu_f(v);
        int l = l0 + j;
        if (l >= LSEQ - (KK - 1)) {
            conv_state[(b * CONVD + c) * (KK - 1) + (l - (LSEQ - (KK - 1)))] = xv[j + 3];
        }
    }
}

// ---------------- dt_p = softplus(dt + dt_bias); dA = exp(dt_p * -exp(A_log)) ----------------
__global__ void dt_kernel(const float* __restrict__ dt_bias,
                          const float* __restrict__ A_log) {
    int idx = blockIdx.x * blockDim.x + threadIdx.x;  // over BT*H
    if (idx >= BT * HH) return;
    int bt = idx >> 6;
    int h  = idx & 63;
    float dtv = g_proj[(size_t)bt * PROJ + (II + CONVD) + h] + dt_bias[h];
    float dtp = softplus_f(dtv);
    float A = -expf(A_log[h]);
    g_dtp[idx] = dtp;
    g_dA[idx] = expf(dtp * A);
}

// ---------------- sequential SSM scan: 1 CTA per (b,h) ----------------
__global__ __launch_bounds__(512, 1)
void scan_kernel(const float* __restrict__ Dv, float* __restrict__ final_state) {
    const int bh = blockIdx.x;
    const int b = bh >> 6, h = bh & 63;
    const int g = h >> 3;
    const int tid = threadIdx.x;
    const int p = tid >> 3;
    const int c = tid & 7;
    const int n0 = c * 16;

    __shared__ float xs[PP];
    __shared__ float Bsm[NN];
    __shared__ float Csm[NN];
    __shared__ float sc[2];

    float st[16];
#pragma unroll
    for (int i = 0; i < 16; i++) st[i] = 0.f;

    const float Dh = Dv[h];
    const size_t xcol = (size_t)h * PP;
    const size_t bcol = (size_t)II + (size_t)g * NN;
    const size_t ccol = (size_t)II + GN + (size_t)g * NN;

    float pref = 0.f, pdA = 0.f, pdtp = 0.f;
    auto load_t = [&](int t) {
        size_t row = ((size_t)b * LSEQ + t) * CONVD;
        if (tid < 64)        pref = g_xbc[row + xcol + tid];
        else if (tid < 192)  pref = g_xbc[row + bcol + (tid - 64)];
        else if (tid < 320)  pref = g_xbc[row + ccol + (tid - 192)];
        else if (tid == 320) {
            int i2 = (b * LSEQ + t) * HH + h;
            pdA = g_dA[i2];
            pdtp = g_dtp[i2];
        }
    };

    load_t(0);
    for (int t = 0; t < LSEQ; t++) {
        __syncthreads();
        if (tid < 64)        xs[tid] = pref;
        else if (tid < 192)  Bsm[tid - 64] = pref;
        else if (tid < 320)  Csm[tid - 192] = pref;
        else if (tid == 320) { sc[0] = pdA; sc[1] = pdtp; }
        __syncthreads();
        if (t + 1 < LSEQ) load_t(t + 1);

        float dAv = sc[0];
        float xp  = xs[p];
        float dtx = sc[1] * xp;
        float yp0 = 0.f, yp1 = 0.f;
#pragma unroll
        for (int i = 0; i < 8; i++) {
            float bn = Bsm[n0 + i];
            float cn = Csm[n0 + i];
            st[i] = fmaf(st[i], dAv, dtx * bn);
            yp0 = fmaf(st[i], cn, yp0);
        }
#pragma unroll
        for (int i = 8; i < 16; i++) {
            float bn = Bsm[n0 + i];
            float cn = Csm[n0 + i];
            st[i] = fmaf(st[i], dAv, dtx * bn);
            yp1 = fmaf(st[i], cn, yp1);
        }
        float yp = yp0 + yp1;
        yp += __shfl_xor_sync(0xffffffffu, yp, 1);
        yp += __shfl_xor_sync(0xffffffffu, yp, 2);
        yp += __shfl_xor_sync(0xffffffffu, yp, 4);
        if (c == 0)
            g_y[((size_t)b * LSEQ + t) * II + (size_t)h * PP + p] = yp + Dh * xp;
    }

#pragma unroll
    for (int i = 0; i < 16; i++)
        final_state[((size_t)bh * PP + p) * NN + n0 + i] = st[i];
}

// ---------------- grouped RMS norm * norm_weight * silu(gate) ----------------
// Output is tf32-rounded (RNA) so both GEMM paths read exact tf32 operands.
__global__ __launch_bounds__(512)
void norm_kernel(const float* __restrict__ nw) {
    const int row = blockIdx.x;
    const int tid = threadIdx.x;
    const float* yr = g_y + (size_t)row * II;

    float v[8];
    float ss = 0.f;
#pragma unroll
    for (int i = 0; i < 8; i++) {
        v[i] = yr[tid * 8 + i];
        ss = fmaf(v[i], v[i], ss);
    }
#pragma unroll
    for (int o = 16; o; o >>= 1) ss += __shfl_xor_sync(0xffffffffu, ss, o);

    __shared__ float wsum[16];
    if ((tid & 31) == 0) wsum[tid >> 5] = ss;
    __syncthreads();
    int gid = tid >> 6;
    float tot = wsum[gid * 2] + wsum[gid * 2 + 1];
    float rs = rsqrtf(tot * (1.0f / GRPSZ) + 1e-5f);

    const float* gr = g_proj + (size_t)row * PROJ;
    float* yo = g_yn + (size_t)row * II;
#pragma unroll
    for (int i = 0; i < 8; i++) {
        int col = tid * 8 + i;
        float gv = gr[col];
        yo[col] = tf32_rna(v[i] * rs * nw[col] * silu_f(gv));
    }
}

// ---------------- launch ----------------
extern "C" void kernel_launch(void* const* d_in, const int* in_sizes, int n_in,
                              void* d_out, int out_size) {
    const float* hs        = (const float*)d_in[0];
    const float* in_proj_w = (const float*)d_in[1];
    const float* conv_w    = (const float*)d_in[2];
    const float* conv_b    = (const float*)d_in[3];
    const float* dt_bias   = (const float*)d_in[4];
    const float* A_log     = (const float*)d_in[5];
    const float* Dv        = (const float*)d_in[6];
    const float* norm_w    = (const float*)d_in[7];
    const float* out_w     = (const float*)d_in[8];

    float* out         = (float*)d_out;
    float* conv_state  = out + OUT_ELEMS;
    float* final_state = conv_state + CS_ELEMS;

    float* pa32; cudaGetSymbolAddress((void**)&pa32, g_a32);
    float* pw32; cudaGetSymbolAddress((void**)&pw32, g_w32);
    float* pproj; cudaGetSymbolAddress((void**)&pproj, g_proj);
    float* pyn;   cudaGetSymbolAddress((void**)&pyn, g_yn);

    // 0. tf32-round A/B operands for in_proj GEMM
    {
        int n4 = (BT * DM) / 4;
        round_tf32_kernel<<<(n4 + 255) / 256, 256>>>(hs, pa32, n4);
    }
    {
        int n4 = (PROJ * DM) / 4;
        round_tf32_kernel<<<(n4 + 255) / 256, 256>>>(in_proj_w, pw32, n4);
    }
    // 1. in_proj GEMM (hybrid tensor+SIMT); 81 col tiles, 56 tensor / 25 SIMT
    {
        dim3 grid((PROJ + 127) / 128, BT / 128);
        gemm_hybrid_kernel<<<grid, 256>>>(pa32, pw32, pproj, BT, PROJ, DM, 56);
    }
    // 2. conv + silu (+ conv_state)
    {
        int total = (BT / 4) * CONVD;
        conv_kernel<<<(total + 255) / 256, 256>>>(conv_w, conv_b, conv_state);
    }
    // 3. dt_p / dA
    {
        int total = BT * HH;
        dt_kernel<<<(total + 255) / 256, 256>>>(dt_bias, A_log);
    }
    // 4. sequential scan (+ final_state)
    scan_kernel<<<BB * HH, 512>>>(Dv, final_state);
    // 5. grouped RMS norm * gate (tf32-rounded output)
    norm_kernel<<<BT, 512>>>(norm_w);
    // 6. round out_proj weight, then out_proj GEMM -> d_out; 32 tiles, 22 tensor / 10 SIMT
    {
        int n4 = (DM * II) / 4;
        round_tf32_kernel<<<(n4 + 255) / 256, 256>>>(out_w, pw32, n4);
    }
    {
        dim3 grid(DM / 128, BT / 128);
        gemm_hybrid_kernel<<<grid, 256>>>(pyn, pw32, out, BT, DM, II, 22);
    }
}

// round 14
// speedup vs baseline: 1.3515x; 1.3515x over previous
#include <cuda_runtime.h>
#include <math.h>
#include <stdint.h>

// ---------------- problem constants ----------------
#define HH 64
#define PP 64
#define NN 128
#define GG 8
#define KK 4
#define DM 4096
#define II 4096           // H*P
#define GN 1024           // G*N
#define CONVD 6144        // I + 2*GN
#define PROJ 10304        // I + CONVD + H
#define LSEQ 2048
#define BB 2
#define BT 4096           // B*L
#define GRPSZ 512         // I/G

#define OUT_ELEMS (4096*4096)
#define CS_ELEMS  (BB*CONVD*(KK-1))

// ---------------- scratch (device globals; no allocs allowed) ----------------
static __device__ float g_proj[(size_t)BT * PROJ];
static __device__ float g_xbc[(size_t)BT * CONVD];
static __device__ float g_dtp[BT * HH];
static __device__ float g_dA[BT * HH];
static __device__ float g_y[(size_t)BT * II];
static __device__ float g_yn[(size_t)BT * II];
static __device__ float g_a32[(size_t)BT * DM];        // tf32-rounded A operand
static __device__ float g_w32[(size_t)PROJ * DM];      // tf32-rounded weights (reused)

__device__ __forceinline__ float silu_f(float x) {
    return x / (1.0f + __expf(-x));
}
__device__ __forceinline__ float softplus_f(float x) {
    return (x > 20.0f) ? x : log1pf(expf(x));
}
__device__ __forceinline__ float tf32_rna(float x) {
    uint32_t r;
    asm("cvt.rna.tf32.f32 %0, %1;" : "=r"(r) : "f"(x));
    return __uint_as_float(r);
}

// ---------------- tf32 rounding pass (RNA, zero-mean error) ----------------
__global__ void round_tf32_kernel(const float* __restrict__ src,
                                  float* __restrict__ dst, int n4) {
    int i = blockIdx.x * blockDim.x + threadIdx.x;
    if (i >= n4) return;
    float4 v = ((const float4*)src)[i];
    v.x = tf32_rna(v.x); v.y = tf32_rna(v.y);
    v.z = tf32_rna(v.z); v.w = tf32_rna(v.w);
    ((float4*)dst)[i] = v;
}

// ---------------- tensor-core tf32 GEMM: C[M,N] = A[M,K] * B[N,K]^T ----------------
// R2 structure with BK=32 (halved per-iter sync/wait overhead).
// CTA 128x128, 256 thr / 8 warps (2x4 of 64x32 warp tiles),
// cp.async double-buffered dynamic smem, row stride 36 floats
// (36 mod 32 = 4 -> fragment banks 4g+tig all distinct, conflict-free).
#define GSTRIDE 36
#define G_STGF  (128 * GSTRIDE)                 // floats per operand stage = 4608
#define GEMM_SMEM_BYTES (4 * G_STGF * 4)        // 2 ops x 2 bufs = 73728 B

__global__ __launch_bounds__(256, 2)
void gemm_tc_kernel(const float* __restrict__ A, const float* __restrict__ B,
                    float* __restrict__ C, int M, int N, int K) {
    extern __shared__ __align__(16) float sm[];
    float* As = sm;                  // [2][128][36]
    float* Bs = sm + 2 * G_STGF;     // [2][128][36]

    const int tid  = threadIdx.x;
    const int warp = tid >> 5, lane = tid & 31;
    const int g    = lane >> 2, tig = lane & 3;
    const int wm   = (warp >> 2) * 64;    // warp m offset (0 or 64)
    const int wn   = (warp & 3) * 32;     // warp n offset
    const int row0 = blockIdx.y * 128;
    const int col0 = blockIdx.x * 128;

    // loaders: 2 threads per row, 16 floats (4x16B) each
    const int lr = tid >> 1;
    const int lc = (tid & 1) * 16;
    const float* Ag = A + (size_t)(row0 + lr) * K + lc;
    const float* Bg = B + (size_t)(col0 + lr) * K + lc;
    const int bsz = ((col0 + lr) < N) ? 16 : 0;   // zero-fill OOB B rows

    float acc[4][4][4];
#pragma unroll
    for (int mt = 0; mt < 4; mt++)
#pragma unroll
        for (int nt = 0; nt < 4; nt++)
#pragma unroll
            for (int i = 0; i < 4; i++) acc[mt][nt][i] = 0.f;

    auto load_tiles = [&](int buf, int kt) {
        uint32_t a_s = (uint32_t)__cvta_generic_to_shared(
            As + buf * G_STGF + lr * GSTRIDE + lc);
        uint32_t b_s = (uint32_t)__cvta_generic_to_shared(
            Bs + buf * G_STGF + lr * GSTRIDE + lc);
        const float* ap = Ag + kt;
        const float* bp = Bg + kt;
#pragma unroll
        for (int q = 0; q < 4; q++) {
            asm volatile("cp.async.cg.shared.global [%0], [%1], 16;\n"
                         :: "r"(a_s + 16 * q), "l"(ap + 4 * q));
            asm volatile("cp.async.cg.shared.global [%0], [%1], 16, %2;\n"
                         :: "r"(b_s + 16 * q), "l"(bp + 4 * q), "r"(bsz));
        }
    };

    const int nk = K / 32;
    load_tiles(0, 0);
    asm volatile("cp.async.commit_group;\n");

    for (int it = 0; it < nk; it++) {
        asm volatile("cp.async.wait_group 0;\n");
        __syncthreads();
        if (it + 1 < nk) {
            load_tiles((it + 1) & 1, (it + 1) * 32);
            asm volatile("cp.async.commit_group;\n");
        }
        const float* Ab = As + (it & 1) * G_STGF;
        const float* Bb = Bs + (it & 1) * G_STGF;
#pragma unroll
        for (int ks = 0; ks < 4; ks++) {
            const int k0 = ks * 8;
            uint32_t af[4][4], bf[4][2];
#pragma unroll
            for (int mt = 0; mt < 4; mt++) {
                int r = wm + mt * 16 + g;
                af[mt][0] = __float_as_uint(Ab[r * GSTRIDE + k0 + tig]);
                af[mt][1] = __float_as_uint(Ab[(r + 8) * GSTRIDE + k0 + tig]);
                af[mt][2] = __float_as_uint(Ab[r * GSTRIDE + k0 + 4 + tig]);
                af[mt][3] = __float_as_uint(Ab[(r + 8) * GSTRIDE + k0 + 4 + tig]);
            }
#pragma unroll
            for (int nt = 0; nt < 4; nt++) {
                int cc = wn + nt * 8 + g;
                bf[nt][0] = __float_as_uint(Bb[cc * GSTRIDE + k0 + tig]);
                bf[nt][1] = __float_as_uint(Bb[cc * GSTRIDE + k0 + 4 + tig]);
            }
#pragma unroll
            for (int mt = 0; mt < 4; mt++)
#pragma unroll
                for (int nt = 0; nt < 4; nt++)
                    asm volatile(
                        "mma.sync.aligned.m16n8k8.row.col.f32.tf32.tf32.f32 "
                        "{%0,%1,%2,%3}, {%4,%5,%6,%7}, {%8,%9}, {%0,%1,%2,%3};\n"
                        : "+f"(acc[mt][nt][0]), "+f"(acc[mt][nt][1]),
                          "+f"(acc[mt][nt][2]), "+f"(acc[mt][nt][3])
                        : "r"(af[mt][0]), "r"(af[mt][1]), "r"(af[mt][2]), "r"(af[mt][3]),
                          "r"(bf[nt][0]), "r"(bf[nt][1]));
        }
    }

#pragma unroll
    for (int mt = 0; mt < 4; mt++) {
        int r = row0 + wm + mt * 16 + g;
#pragma unroll
        for (int nt = 0; nt < 4; nt++) {
            int cc = col0 + wn + nt * 8 + 2 * tig;
            if (cc < N) {   // N even, cc even -> cc+1 also valid
                float* p0 = C + (size_t)r * N + cc;
                float* p1 = C + (size_t)(r + 8) * N + cc;
                p0[0] = acc[mt][nt][0]; p0[1] = acc[mt][nt][1];
                p1[0] = acc[mt][nt][2]; p1[1] = acc[mt][nt][3];
            }
        }
    }
}

// ---------------- conv1d (depthwise, K=4, causal) + silu; 4 outputs/thread ----------------
__global__ void conv_kernel(const float* __restrict__ cw,
                            const float* __restrict__ cb,
                            float* __restrict__ conv_state) {
    int idx = blockIdx.x * blockDim.x + threadIdx.x;   // over (BT/4)*CONVD
    if (idx >= (BT / 4) * CONVD) return;
    int lb = idx / CONVD;
    int c  = idx - lb * CONVD;
    int b  = lb >> 9;                   // 512 l-blocks per batch
    int l0 = (lb & 511) * 4;

    const float w0 = cw[c * 4 + 0], w1 = cw[c * 4 + 1], w2 = cw[c * 4 + 2], w3 = cw[c * 4 + 3];
    const float bias = cb[c];
    const size_t colbase = (size_t)II + c;
    const size_t rowbase = ((size_t)b * LSEQ + l0) * PROJ + colbase;

    float xv[7];
#pragma unroll
    for (int j = 0; j < 3; j++)
        xv[j] = (l0 - 3 + j >= 0) ? g_proj[rowbase + (size_t)(j - 3) * PROJ] : 0.f;
#pragma unroll
    for (int j = 3; j < 7; j++)
        xv[j] = g_proj[rowbase + (size_t)(j - 3) * PROJ];

    size_t obase = ((size_t)b * LSEQ + l0) * CONVD + c;
#pragma unroll
    for (int j = 0; j < 4; j++) {
        float v = bias + xv[j] * w0 + xv[j + 1] * w1 + xv[j + 2] * w2 + xv[j + 3] * w3;
        g_xbc[obase + (size_t)j * CONVD] = silu_f(v);
        int l = l0 + j;
        if (l >= LSEQ - (KK - 1)) {
            conv_state[(b * CONVD + c) * (KK - 1) + (l - (LSEQ - (KK - 1)))] = xv[j + 3];
        }
    }
}

// ---------------- dt_p = softplus(dt + dt_bias); dA = exp(dt_p * -exp(A_log)) ----------------
__global__ void dt_kernel(const float* __restrict__ dt_bias,
                          const float* __restrict__ A_log) {
    int idx = blockIdx.x * blockDim.x + threadIdx.x;  // over BT*H
    if (idx >= BT * HH) return;
    int bt = idx >> 6;
    int h  = idx & 63;
    float dtv = g_proj[(size_t)bt * PROJ + (II + CONVD) + h] + dt_bias[h];
    float dtp = softplus_f(dtv);
    float A = -expf(A_log[h]);
    g_dtp[idx] = dtp;
    g_dA[idx] = expf(dtp * A);
}

// ---------------- sequential SSM scan: 1 CTA per (b,h) ----------------
__global__ __launch_bounds__(512, 1)
void scan_kernel(const float* __restrict__ Dv, float* __restrict__ final_state) {
    const int bh = blockIdx.x;
    const int b = bh >> 6, h = bh & 63;
    const int g = h >> 3;
    const int tid = threadIdx.x;
    const int p = tid >> 3;
    const int c = tid & 7;
    const int n0 = c * 16;

    __shared__ float xs[PP];
    __shared__ float Bsm[NN];
    __shared__ float Csm[NN];
    __shared__ float sc[2];

    float st[16];
#pragma unroll
    for (int i = 0; i < 16; i++) st[i] = 0.f;

    const float Dh = Dv[h];
    const size_t xcol = (size_t)h * PP;
    const size_t bcol = (size_t)II + (size_t)g * NN;
    const size_t ccol = (size_t)II + GN + (size_t)g * NN;

    float pref = 0.f, pdA = 0.f, pdtp = 0.f;
    auto load_t = [&](int t) {
        size_t row = ((size_t)b * LSEQ + t) * CONVD;
        if (tid < 64)        pref = g_xbc[row + xcol + tid];
        else if (tid < 192)  pref = g_xbc[row + bcol + (tid - 64)];
        else if (tid < 320)  pref = g_xbc[row + ccol + (tid - 192)];
        else if (tid == 320) {
            int i2 = (b * LSEQ + t) * HH + h;
            pdA = g_dA[i2];
            pdtp = g_dtp[i2];
        }
    };

    load_t(0);
    for (int t = 0; t < LSEQ; t++) {
        __syncthreads();
        if (tid < 64)        xs[tid] = pref;
        else if (tid < 192)  Bsm[tid - 64] = pref;
        else if (tid < 320)  Csm[tid - 192] = pref;
        else if (tid == 320) { sc[0] = pdA; sc[1] = pdtp; }
        __syncthreads();
        if (t + 1 < LSEQ) load_t(t + 1);

        float dAv = sc[0];
        float xp  = xs[p];
        float dtx = sc[1] * xp;
        float yp0 = 0.f, yp1 = 0.f;
#pragma unroll
        for (int i = 0; i < 8; i++) {
            float bn = Bsm[n0 + i];
            float cn = Csm[n0 + i];
            st[i] = fmaf(st[i], dAv, dtx * bn);
            yp0 = fmaf(st[i], cn, yp0);
        }
#pragma unroll
        for (int i = 8; i < 16; i++) {
            float bn = Bsm[n0 + i];
            float cn = Csm[n0 + i];
            st[i] = fmaf(st[i], dAv, dtx * bn);
            yp1 = fmaf(st[i], cn, yp1);
        }
        float yp = yp0 + yp1;
        yp += __shfl_xor_sync(0xffffffffu, yp, 1);
        yp += __shfl_xor_sync(0xffffffffu, yp, 2);
        yp += __shfl_xor_sync(0xffffffffu, yp, 4);
        if (c == 0)
            g_y[((size_t)b * LSEQ + t) * II + (size_t)h * PP + p] = yp + Dh * xp;
    }

#pragma unroll
    for (int i = 0; i < 16; i++)
        final_state[((size_t)bh * PP + p) * NN + n0 + i] = st[i];
}

// ---------------- grouped RMS norm * norm_weight * silu(gate) ----------------
// Output is tf32-rounded (RNA) so the out_proj GEMM reads exact tf32 operands.
__global__ __launch_bounds__(512)
void norm_kernel(const float* __restrict__ nw) {
    const int row = blockIdx.x;
    const int tid = threadIdx.x;
    const float* yr = g_y + (size_t)row * II;

    float v[8];
    float ss = 0.f;
#pragma unroll
    for (int i = 0; i < 8; i++) {
        v[i] = yr[tid * 8 + i];
        ss = fmaf(v[i], v[i], ss);
    }
#pragma unroll
    for (int o = 16; o; o >>= 1) ss += __shfl_xor_sync(0xffffffffu, ss, o);

    __shared__ float wsum[16];
    if ((tid & 31) == 0) wsum[tid >> 5] = ss;
    __syncthreads();
    int gid = tid >> 6;
    float tot = wsum[gid * 2] + wsum[gid * 2 + 1];
    float rs = rsqrtf(tot * (1.0f / GRPSZ) + 1e-5f);

    const float* gr = g_proj + (size_t)row * PROJ;
    float* yo = g_yn + (size_t)row * II;
#pragma unroll
    for (int i = 0; i < 8; i++) {
        int col = tid * 8 + i;
        float gv = gr[col];
        yo[col] = tf32_rna(v[i] * rs * nw[col] * silu_f(gv));
    }
}

// ---------------- launch ----------------
extern "C" void kernel_launch(void* const* d_in, const int* in_sizes, int n_in,
                              void* d_out, int out_size) {
    const float* hs        = (const float*)d_in[0];
    const float* in_proj_w = (const float*)d_in[1];
    const float* conv_w    = (const float*)d_in[2];
    const float* conv_b    = (const float*)d_in[3];
    const float* dt_bias   = (const float*)d_in[4];
    const float* A_log     = (const float*)d_in[5];
    const float* Dv        = (const float*)d_in[6];
    const float* norm_w    = (const float*)d_in[7];
    const float* out_w     = (const float*)d_in[8];

    float* out         = (float*)d_out;
    float* conv_state  = out + OUT_ELEMS;
    float* final_state = conv_state + CS_ELEMS;

    static int inited = 0;
    if (!inited) {
        cudaFuncSetAttribute(gemm_tc_kernel,
                             cudaFuncAttributeMaxDynamicSharedMemorySize,
                             GEMM_SMEM_BYTES);
        inited = 1;
    }

    float* pa32; cudaGetSymbolAddress((void**)&pa32, g_a32);
    float* pw32; cudaGetSymbolAddress((void**)&pw32, g_w32);
    float* pproj; cudaGetSymbolAddress((void**)&pproj, g_proj);
    float* pyn;   cudaGetSymbolAddress((void**)&pyn, g_yn);

    // 0. tf32-round A/B operands for in_proj GEMM
    {
        int n4 = (BT * DM) / 4;
        round_tf32_kernel<<<(n4 + 255) / 256, 256>>>(hs, pa32, n4);
    }
    {
        int n4 = (PROJ * DM) / 4;
        round_tf32_kernel<<<(n4 + 255) / 256, 256>>>(in_proj_w, pw32, n4);
    }
    // 1. in_proj GEMM (tensor cores, tf32, BK=32)
    {
        dim3 grid((PROJ + 127) / 128, BT / 128);
        gemm_tc_kernel<<<grid, 256, GEMM_SMEM_BYTES>>>(pa32, pw32, pproj, BT, PROJ, DM);
    }
    // 2. conv + silu (+ conv_state)
    {
        int total = (BT / 4) * CONVD;
        conv_kernel<<<(total + 255) / 256, 256>>>(conv_w, conv_b, conv_state);
    }
    // 3. dt_p / dA
    {
        int total = BT * HH;
        dt_kernel<<<(total + 255) / 256, 256>>>(dt_bias, A_log);
    }
    // 4. sequential scan (+ final_state)
    scan_kernel<<<BB * HH, 512>>>(Dv, final_state);
    // 5. grouped RMS norm * gate (tf32-rounded output)
    norm_kernel<<<BT, 512>>>(norm_w);
    // 6. round out_proj weight, then out_proj GEMM -> d_out
    {
        int n4 = (DM * II) / 4;
        round_tf32_kernel<<<(n4 + 255) / 256, 256>>>(out_w, pw32, n4);
    }
    {
        dim3 grid(DM / 128, BT / 128);
        gemm_tc_kernel<<<grid, 256, GEMM_SMEM_BYTES>>>(pyn, pw32, out, BT, DM, II);
    }
}

// round 16
// speedup vs baseline: 1.9381x; 1.4340x over previous
#include <cuda_runtime.h>
#include <cuda_fp16.h>
#include <math.h>
#include <stdint.h>

// ---------------- problem constants ----------------
#define HH 64
#define PP 64
#define NN 128
#define GG 8
#define KK 4
#define DM 4096
#define II 4096           // H*P
#define GN 1024           // G*N
#define CONVD 6144        // I + 2*GN
#define PROJ 10304        // I + CONVD + H
#define LSEQ 2048
#define BB 2
#define BT 4096           // B*L
#define GRPSZ 512         // I/G

#define OUT_ELEMS (4096*4096)
#define CS_ELEMS  (BB*CONVD*(KK-1))

// ---------------- scratch (device globals; no allocs allowed) ----------------
static __device__ float  g_proj[(size_t)BT * PROJ];
static __device__ float  g_xbc[(size_t)BT * CONVD];
static __device__ float  g_dtp[BT * HH];
static __device__ float  g_dA[BT * HH];
static __device__ float  g_y[(size_t)BT * II];
static __device__ __half g_a16[(size_t)BT * DM];       // fp16 A operand (hs, then yn)
static __device__ __half g_w16[(size_t)PROJ * DM];     // fp16 weights (reused)

__device__ __forceinline__ float silu_f(float x) {
    return x / (1.0f + __expf(-x));
}
__device__ __forceinline__ float softplus_f(float x) {
    return (x > 20.0f) ? x : log1pf(expf(x));
}

// ---------------- fp32 -> fp16 conversion (RN) ----------------
__global__ void tohalf_kernel(const float* __restrict__ src,
                              __half* __restrict__ dst, int n4) {
    int i = blockIdx.x * blockDim.x + threadIdx.x;
    if (i >= n4) return;
    float4 v = ((const float4*)src)[i];
    __half2* d = (__half2*)dst;
    d[2 * i]     = __floats2half2_rn(v.x, v.y);
    d[2 * i + 1] = __floats2half2_rn(v.z, v.w);
}

// ---------------- tensor-core fp16 GEMM: C[M,N] = A[M,K] * B[N,K]^T ----------------
// R2 structure, fp16 operands, m16n8k16 (2x MACs per issued MMA vs tf32 k8).
// CTA 128x128, BK=16, 256 thr / 8 warps (2x4 of 64x32 warp tiles),
// cp.async double-buffered, smem row stride 40 halves
// (bank of frag load = (20g + tig) mod 32 -> all 32 distinct, conflict-free).
#define GSTRIDE 40                       // halves per row
#define G_STGH  (128 * GSTRIDE)          // halves per operand stage = 5120

__global__ __launch_bounds__(256, 2)
void gemm_h_kernel(const __half* __restrict__ A, const __half* __restrict__ B,
                   float* __restrict__ C, int M, int N, int K) {
    __shared__ __align__(16) __half As[2 * G_STGH];
    __shared__ __align__(16) __half Bs[2 * G_STGH];

    const int tid  = threadIdx.x;
    const int warp = tid >> 5, lane = tid & 31;
    const int g    = lane >> 2, tig = lane & 3;
    const int wm   = (warp >> 2) * 64;    // warp m offset (0 or 64)
    const int wn   = (warp & 3) * 32;     // warp n offset
    const int row0 = blockIdx.y * 128;
    const int col0 = blockIdx.x * 128;

    // loaders: 2 threads per row, 8 halves (one 16B chunk) each
    const int lr = tid >> 1;
    const int lc = (tid & 1) * 8;
    const __half* Ag = A + (size_t)(row0 + lr) * K + lc;
    const __half* Bg = B + (size_t)(col0 + lr) * K + lc;
    const int bsz = ((col0 + lr) < N) ? 16 : 0;   // zero-fill OOB B rows

    float acc[4][4][4];
#pragma unroll
    for (int mt = 0; mt < 4; mt++)
#pragma unroll
        for (int nt = 0; nt < 4; nt++)
#pragma unroll
            for (int i = 0; i < 4; i++) acc[mt][nt][i] = 0.f;

    auto load_tiles = [&](int buf, int kt) {
        uint32_t a_s = (uint32_t)__cvta_generic_to_shared(
            As + buf * G_STGH + lr * GSTRIDE + lc);
        uint32_t b_s = (uint32_t)__cvta_generic_to_shared(
            Bs + buf * G_STGH + lr * GSTRIDE + lc);
        const __half* ap = Ag + kt;
        const __half* bp = Bg + kt;
        asm volatile("cp.async.cg.shared.global [%0], [%1], 16;\n" :: "r"(a_s), "l"(ap));
        asm volatile("cp.async.cg.shared.global [%0], [%1], 16, %2;\n" :: "r"(b_s), "l"(bp), "r"(bsz));
    };

    const int nk = K / 16;
    load_tiles(0, 0);
    asm volatile("cp.async.commit_group;\n");

    for (int it = 0; it < nk; it++) {
        asm volatile("cp.async.wait_group 0;\n");
        __syncthreads();
        if (it + 1 < nk) {
            load_tiles((it + 1) & 1, (it + 1) * 16);
            asm volatile("cp.async.commit_group;\n");
        }
        const __half* Ab = As + (it & 1) * G_STGH;
        const __half* Bb = Bs + (it & 1) * G_STGH;

        uint32_t af[4][4], bf[4][2];
#pragma unroll
        for (int mt = 0; mt < 4; mt++) {
            int r = wm + mt * 16 + g;
            af[mt][0] = *(const uint32_t*)(Ab + r * GSTRIDE + 2 * tig);
            af[mt][1] = *(const uint32_t*)(Ab + (r + 8) * GSTRIDE + 2 * tig);
            af[mt][2] = *(const uint32_t*)(Ab + r * GSTRIDE + 8 + 2 * tig);
            af[mt][3] = *(const uint32_t*)(Ab + (r + 8) * GSTRIDE + 8 + 2 * tig);
        }
#pragma unroll
        for (int nt = 0; nt < 4; nt++) {
            int cc = wn + nt * 8 + g;
            bf[nt][0] = *(const uint32_t*)(Bb + cc * GSTRIDE + 2 * tig);
            bf[nt][1] = *(const uint32_t*)(Bb + cc * GSTRIDE + 8 + 2 * tig);
        }
#pragma unroll
        for (int mt = 0; mt < 4; mt++)
#pragma unroll
            for (int nt = 0; nt < 4; nt++)
                asm volatile(
                    "mma.sync.aligned.m16n8k16.row.col.f32.f16.f16.f32 "
                    "{%0,%1,%2,%3}, {%4,%5,%6,%7}, {%8,%9}, {%0,%1,%2,%3};\n"
                    : "+f"(acc[mt][nt][0]), "+f"(acc[mt][nt][1]),
                      "+f"(acc[mt][nt][2]), "+f"(acc[mt][nt][3])
                    : "r"(af[mt][0]), "r"(af[mt][1]), "r"(af[mt][2]), "r"(af[mt][3]),
                      "r"(bf[nt][0]), "r"(bf[nt][1]));
    }

#pragma unroll
    for (int mt = 0; mt < 4; mt++) {
        int r = row0 + wm + mt * 16 + g;
#pragma unroll
        for (int nt = 0; nt < 4; nt++) {
            int cc = col0 + wn + nt * 8 + 2 * tig;
            if (cc < N) {   // N even, cc even -> cc+1 also valid
                float* p0 = C + (size_t)r * N + cc;
                float* p1 = C + (size_t)(r + 8) * N + cc;
                p0[0] = acc[mt][nt][0]; p0[1] = acc[mt][nt][1];
                p1[0] = acc[mt][nt][2]; p1[1] = acc[mt][nt][3];
            }
        }
    }
}

// ---------------- conv1d (depthwise, K=4, causal) + silu; 4 outputs/thread ----------------
__global__ void conv_kernel(const float* __restrict__ cw,
                            const float* __restrict__ cb,
                            float* __restrict__ conv_state) {
    int idx = blockIdx.x * blockDim.x + threadIdx.x;   // over (BT/4)*CONVD
    if (idx >= (BT / 4) * CONVD) return;
    int lb = idx / CONVD;
    int c  = idx - lb * CONVD;
    int b  = lb >> 9;                   // 512 l-blocks per batch
    int l0 = (lb & 511) * 4;

    const float w0 = cw[c * 4 + 0], w1 = cw[c * 4 + 1], w2 = cw[c * 4 + 2], w3 = cw[c * 4 + 3];
    const float bias = cb[c];
    const size_t colbase = (size_t)II + c;
    const size_t rowbase = ((size_t)b * LSEQ + l0) * PROJ + colbase;

    float xv[7];
#pragma unroll
    for (int j = 0; j < 3; j++)
        xv[j] = (l0 - 3 + j >= 0) ? g_proj[rowbase + (size_t)(j - 3) * PROJ] : 0.f;
#pragma unroll
    for (int j = 3; j < 7; j++)
        xv[j] = g_proj[rowbase + (size_t)(j - 3) * PROJ];

    size_t obase = ((size_t)b * LSEQ + l0) * CONVD + c;
#pragma unroll
    for (int j = 0; j < 4; j++) {
        float v = bias + xv[j] * w0 + xv[j + 1] * w1 + xv[j + 2] * w2 + xv[j + 3] * w3;
        g_xbc[obase + (size_t)j * CONVD] = silu_f(v);
        int l = l0 + j;
        if (l >= LSEQ - (KK - 1)) {
            conv_state[(b * CONVD + c) * (KK - 1) + (l - (LSEQ - (KK - 1)))] = xv[j + 3];
        }
    }
}

// ---------------- dt_p = softplus(dt + dt_bias); dA = exp(dt_p * -exp(A_log)) ----------------
__global__ void dt_kernel(const float* __restrict__ dt_bias,
                          const float* __restrict__ A_log) {
    int idx = blockIdx.x * blockDim.x + threadIdx.x;  // over BT*H
    if (idx >= BT * HH) return;
    int bt = idx >> 6;
    int h  = idx & 63;
    float dtv = g_proj[(size_t)bt * PROJ + (II + CONVD) + h] + dt_bias[h];
    float dtp = softplus_f(dtv);
    float A = -expf(A_log[h]);
    g_dtp[idx] = dtp;
    g_dA[idx] = expf(dtp * A);
}

// ---------------- sequential SSM scan: 1 CTA per (b,h) ----------------
__global__ __launch_bounds__(512, 1)
void scan_kernel(const float* __restrict__ Dv, float* __restrict__ final_state) {
    const int bh = blockIdx.x;
    const int b = bh >> 6, h = bh & 63;
    const int g = h >> 3;
    const int tid = threadIdx.x;
    const int p = tid >> 3;
    const int c = tid & 7;
    const int n0 = c * 16;

    __shared__ float xs[PP];
    __shared__ float Bsm[NN];
    __shared__ float Csm[NN];
    __shared__ float sc[2];

    float st[16];
#pragma unroll
    for (int i = 0; i < 16; i++) st[i] = 0.f;

    const float Dh = Dv[h];
    const size_t xcol = (size_t)h * PP;
    const size_t bcol = (size_t)II + (size_t)g * NN;
    const size_t ccol = (size_t)II + GN + (size_t)g * NN;

    float pref = 0.f, pdA = 0.f, pdtp = 0.f;
    auto load_t = [&](int t) {
        size_t row = ((size_t)b * LSEQ + t) * CONVD;
        if (tid < 64)        pref = g_xbc[row + xcol + tid];
        else if (tid < 192)  pref = g_xbc[row + bcol + (tid - 64)];
        else if (tid < 320)  pref = g_xbc[row + ccol + (tid - 192)];
        else if (tid == 320) {
            int i2 = (b * LSEQ + t) * HH + h;
            pdA = g_dA[i2];
            pdtp = g_dtp[i2];
        }
    };

    load_t(0);
    for (int t = 0; t < LSEQ; t++) {
        __syncthreads();
        if (tid < 64)        xs[tid] = pref;
        else if (tid < 192)  Bsm[tid - 64] = pref;
        else if (tid < 320)  Csm[tid - 192] = pref;
        else if (tid == 320) { sc[0] = pdA; sc[1] = pdtp; }
        __syncthreads();
        if (t + 1 < LSEQ) load_t(t + 1);

        float dAv = sc[0];
        float xp  = xs[p];
        float dtx = sc[1] * xp;
        float yp0 = 0.f, yp1 = 0.f;
#pragma unroll
        for (int i = 0; i < 8; i++) {
            float bn = Bsm[n0 + i];
            float cn = Csm[n0 + i];
            st[i] = fmaf(st[i], dAv, dtx * bn);
            yp0 = fmaf(st[i], cn, yp0);
        }
#pragma unroll
        for (int i = 8; i < 16; i++) {
            float bn = Bsm[n0 + i];
            float cn = Csm[n0 + i];
            st[i] = fmaf(st[i], dAv, dtx * bn);
            yp1 = fmaf(st[i], cn, yp1);
        }
        float yp = yp0 + yp1;
        yp += __shfl_xor_sync(0xffffffffu, yp, 1);
        yp += __shfl_xor_sync(0xffffffffu, yp, 2);
        yp += __shfl_xor_sync(0xffffffffu, yp, 4);
        if (c == 0)
            g_y[((size_t)b * LSEQ + t) * II + (size_t)h * PP + p] = yp + Dh * xp;
    }

#pragma unroll
    for (int i = 0; i < 16; i++)
        final_state[((size_t)bh * PP + p) * NN + n0 + i] = st[i];
}

// ---------------- grouped RMS norm * norm_weight * silu(gate) -> fp16 ----------------
// Writes the out_proj A operand directly in fp16 (RN).
__global__ __launch_bounds__(512)
void norm_kernel(const float* __restrict__ nw) {
    const int row = blockIdx.x;
    const int tid = threadIdx.x;
    const float* yr = g_y + (size_t)row * II;

    float v[8];
    float ss = 0.f;
#pragma unroll
    for (int i = 0; i < 8; i++) {
        v[i] = yr[tid * 8 + i];
        ss = fmaf(v[i], v[i], ss);
    }
#pragma unroll
    for (int o = 16; o; o >>= 1) ss += __shfl_xor_sync(0xffffffffu, ss, o);

    __shared__ float wsum[16];
    if ((tid & 31) == 0) wsum[tid >> 5] = ss;
    __syncthreads();
    int gid = tid >> 6;
    float tot = wsum[gid * 2] + wsum[gid * 2 + 1];
    float rs = rsqrtf(tot * (1.0f / GRPSZ) + 1e-5f);

    const float* gr = g_proj + (size_t)row * PROJ;
    __half2* yo = (__half2*)(g_a16 + (size_t)row * II);
#pragma unroll
    for (int i = 0; i < 4; i++) {
        int col = tid * 8 + 2 * i;
        float z0 = v[2*i]     * rs * nw[col]     * silu_f(gr[col]);
        float z1 = v[2*i + 1] * rs * nw[col + 1] * silu_f(gr[col + 1]);
        yo[tid * 4 + i] = __floats2half2_rn(z0, z1);
    }
}

// ---------------- launch ----------------
extern "C" void kernel_launch(void* const* d_in, const int* in_sizes, int n_in,
                              void* d_out, int out_size) {
    const float* hs        = (const float*)d_in[0];
    const float* in_proj_w = (const float*)d_in[1];
    const float* conv_w    = (const float*)d_in[2];
    const float* conv_b    = (const float*)d_in[3];
    const float* dt_bias   = (const float*)d_in[4];
    const float* A_log     = (const float*)d_in[5];
    const float* Dv        = (const float*)d_in[6];
    const float* norm_w    = (const float*)d_in[7];
    const float* out_w     = (const float*)d_in[8];

    float* out         = (float*)d_out;
    float* conv_state  = out + OUT_ELEMS;
    float* final_state = conv_state + CS_ELEMS;

    __half* pa16; cudaGetSymbolAddress((void**)&pa16, g_a16);
    __half* pw16; cudaGetSymbolAddress((void**)&pw16, g_w16);
    float* pproj; cudaGetSymbolAddress((void**)&pproj, g_proj);

    // 0. fp32 -> fp16 operands for in_proj GEMM
    {
        int n4 = (BT * DM) / 4;
        tohalf_kernel<<<(n4 + 255) / 256, 256>>>(hs, pa16, n4);
    }
    {
        int n4 = (PROJ * DM) / 4;
        tohalf_kernel<<<(n4 + 255) / 256, 256>>>(in_proj_w, pw16, n4);
    }
    // 1. in_proj GEMM (fp16 tensor cores, fp32 accum)
    {
        dim3 grid((PROJ + 127) / 128, BT / 128);
        gemm_h_kernel<<<grid, 256>>>(pa16, pw16, pproj, BT, PROJ, DM);
    }
    // 2. conv + silu (+ conv_state)
    {
        int total = (BT / 4) * CONVD;
        conv_kernel<<<(total + 255) / 256, 256>>>(conv_w, conv_b, conv_state);
    }
    // 3. dt_p / dA
    {
        int total = BT * HH;
        dt_kernel<<<(total + 255) / 256, 256>>>(dt_bias, A_log);
    }
    // 4. sequential scan (+ final_state)
    scan_kernel<<<BB * HH, 512>>>(Dv, final_state);
    // 5. grouped RMS norm * gate -> fp16 A operand
    norm_kernel<<<BT, 512>>>(norm_w);
    // 6. out_proj weight -> fp16, then out_proj GEMM -> d_out
    {
        int n4 = (DM * II) / 4;
        tohalf_kernel<<<(n4 + 255) / 256, 256>>>(out_w, pw16, n4);
    }
    {
        dim3 grid(DM / 128, BT / 128);
        gemm_h_kernel<<<grid, 256>>>(pa16, pw16, out, BT, DM, II);
    }
}

// round 17
// speedup vs baseline: 1.9885x; 1.0260x over previous
#include <cuda_runtime.h>
#include <cuda_fp16.h>
#include <math.h>
#include <stdint.h>

// ---------------- problem constants ----------------
#define HH 64
#define PP 64
#define NN 128
#define GG 8
#define KK 4
#define DM 4096
#define II 4096           // H*P
#define GN 1024           // G*N
#define CONVD 6144        // I + 2*GN
#define PROJ 10304        // I + CONVD + H
#define LSEQ 2048
#define BB 2
#define BT 4096           // B*L
#define GRPSZ 512         // I/G

#define OUT_ELEMS (4096*4096)
#define CS_ELEMS  (BB*CONVD*(KK-1))

// ---------------- scratch (device globals; no allocs allowed) ----------------
static __device__ float  g_proj[(size_t)BT * PROJ];
static __device__ float  g_xbc[(size_t)BT * CONVD];
static __device__ float  g_dtp[BT * HH];
static __device__ float  g_dA[BT * HH];
static __device__ float  g_y[(size_t)BT * II];
static __device__ __half g_a16[(size_t)BT * DM];       // fp16 A operand (hs, then yn)
static __device__ __half g_w16[(size_t)PROJ * DM];     // fp16 weights (reused)

__device__ __forceinline__ float silu_f(float x) {
    return x / (1.0f + __expf(-x));
}
__device__ __forceinline__ float softplus_f(float x) {
    return (x > 20.0f) ? x : log1pf(expf(x));
}

// ---------------- fp32 -> fp16 conversion (RN) ----------------
__global__ void tohalf_kernel(const float* __restrict__ src,
                              __half* __restrict__ dst, int n4) {
    int i = blockIdx.x * blockDim.x + threadIdx.x;
    if (i >= n4) return;
    float4 v = ((const float4*)src)[i];
    __half2* d = (__half2*)dst;
    d[2 * i]     = __floats2half2_rn(v.x, v.y);
    d[2 * i + 1] = __floats2half2_rn(v.z, v.w);
}

// ---------------- tensor-core fp16 GEMM: C[M,N] = A[M,K] * B[N,K]^T ----------------
// R16 structure, 3-stage cp.async pipeline (wait_group 1 -> wait always hits a
// group issued 2 iters ago; zero exposed load latency). Loop body, strides,
// loader assignment identical to the passing R16 kernel.
// CTA 128x128, BK=16, 256 thr / 8 warps (2x4 of 64x32 warp tiles),
// smem row stride 40 halves (frag banks (20g+tig) mod 32 all distinct).
#define GSTRIDE 40                       // halves per row
#define G_STGH  (128 * GSTRIDE)          // halves per operand stage = 5120
#define GEMM_SMEM_BYTES (6 * G_STGH * 2) // 2 ops x 3 stages x 5120 halves = 61440 B

__global__ __launch_bounds__(256, 2)
void gemm_h_kernel(const __half* __restrict__ A, const __half* __restrict__ B,
                   float* __restrict__ C, int M, int N, int K) {
    extern __shared__ __align__(16) __half smh[];
    __half* As = smh;                    // [3][128][40]
    __half* Bs = smh + 3 * G_STGH;       // [3][128][40]

    const int tid  = threadIdx.x;
    const int warp = tid >> 5, lane = tid & 31;
    const int g    = lane >> 2, tig = lane & 3;
    const int wm   = (warp >> 2) * 64;    // warp m offset (0 or 64)
    const int wn   = (warp & 3) * 32;     // warp n offset
    const int row0 = blockIdx.y * 128;
    const int col0 = blockIdx.x * 128;

    // loaders: 2 threads per row, 8 halves (one 16B chunk) each
    const int lr = tid >> 1;
    const int lc = (tid & 1) * 8;
    const __half* Ag = A + (size_t)(row0 + lr) * K + lc;
    const __half* Bg = B + (size_t)(col0 + lr) * K + lc;
    const int bsz = ((col0 + lr) < N) ? 16 : 0;   // zero-fill OOB B rows

    float acc[4][4][4];
#pragma unroll
    for (int mt = 0; mt < 4; mt++)
#pragma unroll
        for (int nt = 0; nt < 4; nt++)
#pragma unroll
            for (int i = 0; i < 4; i++) acc[mt][nt][i] = 0.f;

    auto load_tiles = [&](int buf, int kt) {
        uint32_t a_s = (uint32_t)__cvta_generic_to_shared(
            As + buf * G_STGH + lr * GSTRIDE + lc);
        uint32_t b_s = (uint32_t)__cvta_generic_to_shared(
            Bs + buf * G_STGH + lr * GSTRIDE + lc);
        const __half* ap = Ag + kt;
        const __half* bp = Bg + kt;
        asm volatile("cp.async.cg.shared.global [%0], [%1], 16;\n" :: "r"(a_s), "l"(ap));
        asm volatile("cp.async.cg.shared.global [%0], [%1], 16, %2;\n" :: "r"(b_s), "l"(bp), "r"(bsz));
    };

    const int nk = K / 16;
    load_tiles(0, 0);
    asm volatile("cp.async.commit_group;\n");
    load_tiles(1, 16);
    asm volatile("cp.async.commit_group;\n");

    int buf = 0;
    for (int it = 0; it < nk; it++) {
        asm volatile("cp.async.wait_group 1;\n");   // stage `it` complete (issued 2 iters ago)
        __syncthreads();                            // visibility + protects buf reuse
        if (it + 2 < nk) {
            load_tiles((buf + 2) % 3, (it + 2) * 16);
            asm volatile("cp.async.commit_group;\n");
        } else {
            asm volatile("cp.async.commit_group;\n");  // empty group keeps wait count aligned
        }
        const __half* Ab = As + buf * G_STGH;
        const __half* Bb = Bs + buf * G_STGH;

        uint32_t af[4][4], bf[4][2];
#pragma unroll
        for (int mt = 0; mt < 4; mt++) {
            int r = wm + mt * 16 + g;
            af[mt][0] = *(const uint32_t*)(Ab + r * GSTRIDE + 2 * tig);
            af[mt][1] = *(const uint32_t*)(Ab + (r + 8) * GSTRIDE + 2 * tig);
            af[mt][2] = *(const uint32_t*)(Ab + r * GSTRIDE + 8 + 2 * tig);
            af[mt][3] = *(const uint32_t*)(Ab + (r + 8) * GSTRIDE + 8 + 2 * tig);
        }
#pragma unroll
        for (int nt = 0; nt < 4; nt++) {
            int cc = wn + nt * 8 + g;
            bf[nt][0] = *(const uint32_t*)(Bb + cc * GSTRIDE + 2 * tig);
            bf[nt][1] = *(const uint32_t*)(Bb + cc * GSTRIDE + 8 + 2 * tig);
        }
#pragma unroll
        for (int mt = 0; mt < 4; mt++)
#pragma unroll
            for (int nt = 0; nt < 4; nt++)
                asm volatile(
                    "mma.sync.aligned.m16n8k16.row.col.f32.f16.f16.f32 "
                    "{%0,%1,%2,%3}, {%4,%5,%6,%7}, {%8,%9}, {%0,%1,%2,%3};\n"
                    : "+f"(acc[mt][nt][0]), "+f"(acc[mt][nt][1]),
                      "+f"(acc[mt][nt][2]), "+f"(acc[mt][nt][3])
                    : "r"(af[mt][0]), "r"(af[mt][1]), "r"(af[mt][2]), "r"(af[mt][3]),
                      "r"(bf[nt][0]), "r"(bf[nt][1]));
        buf = (buf + 1) % 3;
    }

#pragma unroll
    for (int mt = 0; mt < 4; mt++) {
        int r = row0 + wm + mt * 16 + g;
#pragma unroll
        for (int nt = 0; nt < 4; nt++) {
            int cc = col0 + wn + nt * 8 + 2 * tig;
            if (cc < N) {   // N even, cc even -> cc+1 also valid
                float* p0 = C + (size_t)r * N + cc;
                float* p1 = C + (size_t)(r + 8) * N + cc;
                p0[0] = acc[mt][nt][0]; p0[1] = acc[mt][nt][1];
                p1[0] = acc[mt][nt][2]; p1[1] = acc[mt][nt][3];
            }
        }
    }
}

// ---------------- conv1d (depthwise, K=4, causal) + silu; 4 outputs/thread ----------------
__global__ void conv_kernel(const float* __restrict__ cw,
                            const float* __restrict__ cb,
                            float* __restrict__ conv_state) {
    int idx = blockIdx.x * blockDim.x + threadIdx.x;   // over (BT/4)*CONVD
    if (idx >= (BT / 4) * CONVD) return;
    int lb = idx / CONVD;
    int c  = idx - lb * CONVD;
    int b  = lb >> 9;                   // 512 l-blocks per batch
    int l0 = (lb & 511) * 4;

    const float w0 = cw[c * 4 + 0], w1 = cw[c * 4 + 1], w2 = cw[c * 4 + 2], w3 = cw[c * 4 + 3];
    const float bias = cb[c];
    const size_t colbase = (size_t)II + c;
    const size_t rowbase = ((size_t)b * LSEQ + l0) * PROJ + colbase;

    float xv[7];
#pragma unroll
    for (int j = 0; j < 3; j++)
        xv[j] = (l0 - 3 + j >= 0) ? g_proj[rowbase + (size_t)(j - 3) * PROJ] : 0.f;
#pragma unroll
    for (int j = 3; j < 7; j++)
        xv[j] = g_proj[rowbase + (size_t)(j - 3) * PROJ];

    size_t obase = ((size_t)b * LSEQ + l0) * CONVD + c;
#pragma unroll
    for (int j = 0; j < 4; j++) {
        float v = bias + xv[j] * w0 + xv[j + 1] * w1 + xv[j + 2] * w2 + xv[j + 3] * w3;
        g_xbc[obase + (size_t)j * CONVD] = silu_f(v);
        int l = l0 + j;
        if (l >= LSEQ - (KK - 1)) {
            conv_state[(b * CONVD + c) * (KK - 1) + (l - (LSEQ - (KK - 1)))] = xv[j + 3];
        }
    }
}

// ---------------- dt_p = softplus(dt + dt_bias); dA = exp(dt_p * -exp(A_log)) ----------------
__global__ void dt_kernel(const float* __restrict__ dt_bias,
                          const float* __restrict__ A_log) {
    int idx = blockIdx.x * blockDim.x + threadIdx.x;  // over BT*H
    if (idx >= BT * HH) return;
    int bt = idx >> 6;
    int h  = idx & 63;
    float dtv = g_proj[(size_t)bt * PROJ + (II + CONVD) + h] + dt_bias[h];
    float dtp = softplus_f(dtv);
    float A = -expf(A_log[h]);
    g_dtp[idx] = dtp;
    g_dA[idx] = expf(dtp * A);
}

// ---------------- sequential SSM scan: 1 CTA per (b,h) ----------------
// Double-buffered smem staging: ONE __syncthreads per timestep.
__global__ __launch_bounds__(512, 1)
void scan_kernel(const float* __restrict__ Dv, float* __restrict__ final_state) {
    const int bh = blockIdx.x;
    const int b = bh >> 6, h = bh & 63;
    const int g = h >> 3;
    const int tid = threadIdx.x;
    const int p = tid >> 3;
    const int c = tid & 7;
    const int n0 = c * 16;

    __shared__ float xs[2][PP];
    __shared__ float Bsm[2][NN];
    __shared__ float Csm[2][NN];
    __shared__ float sc[2][2];

    float st[16];
#pragma unroll
    for (int i = 0; i < 16; i++) st[i] = 0.f;

    const float Dh = Dv[h];
    const size_t xcol = (size_t)h * PP;
    const size_t bcol = (size_t)II + (size_t)g * NN;
    const size_t ccol = (size_t)II + GN + (size_t)g * NN;

    float pref = 0.f, pdA = 0.f, pdtp = 0.f;
    auto load_t = [&](int t) {
        size_t row = ((size_t)b * LSEQ + t) * CONVD;
        if (tid < 64)        pref = g_xbc[row + xcol + tid];
        else if (tid < 192)  pref = g_xbc[row + bcol + (tid - 64)];
        else if (tid < 320)  pref = g_xbc[row + ccol + (tid - 192)];
        else if (tid == 320) {
            int i2 = (b * LSEQ + t) * HH + h;
            pdA = g_dA[i2];
            pdtp = g_dtp[i2];
        }
    };

    load_t(0);
    for (int t = 0; t < LSEQ; t++) {
        const int bf = t & 1;
        // stage t's data (buffer reuse distance 2, protected by the sync below)
        if (tid < 64)        xs[bf][tid] = pref;
        else if (tid < 192)  Bsm[bf][tid - 64] = pref;
        else if (tid < 320)  Csm[bf][tid - 192] = pref;
        else if (tid == 320) { sc[bf][0] = pdA; sc[bf][1] = pdtp; }
        __syncthreads();
        if (t + 1 < LSEQ) load_t(t + 1);

        float dAv = sc[bf][0];
        float xp  = xs[bf][p];
        float dtx = sc[bf][1] * xp;
        float yp0 = 0.f, yp1 = 0.f;
#pragma unroll
        for (int i = 0; i < 8; i++) {
            float bn = Bsm[bf][n0 + i];
            float cn = Csm[bf][n0 + i];
            st[i] = fmaf(st[i], dAv, dtx * bn);
            yp0 = fmaf(st[i], cn, yp0);
        }
#pragma unroll
        for (int i = 8; i < 16; i++) {
            float bn = Bsm[bf][n0 + i];
            float cn = Csm[bf][n0 + i];
            st[i] = fmaf(st[i], dAv, dtx * bn);
            yp1 = fmaf(st[i], cn, yp1);
        }
        float yp = yp0 + yp1;
        yp += __shfl_xor_sync(0xffffffffu, yp, 1);
        yp += __shfl_xor_sync(0xffffffffu, yp, 2);
        yp += __shfl_xor_sync(0xffffffffu, yp, 4);
        if (c == 0)
            g_y[((size_t)b * LSEQ + t) * II + (size_t)h * PP + p] = yp + Dh * xp;
    }

#pragma unroll
    for (int i = 0; i < 16; i++)
        final_state[((size_t)bh * PP + p) * NN + n0 + i] = st[i];
}

// ---------------- grouped RMS norm * norm_weight * silu(gate) -> fp16 ----------------
__global__ __launch_bounds__(512)
void norm_kernel(const float* __restrict__ nw) {
    const int row = blockIdx.x;
    const int tid = threadIdx.x;
    const float* yr = g_y + (size_t)row * II;

    float v[8];
    float ss = 0.f;
#pragma unroll
    for (int i = 0; i < 8; i++) {
        v[i] = yr[tid * 8 + i];
        ss = fmaf(v[i], v[i], ss);
    }
#pragma unroll
    for (int o = 16; o; o >>= 1) ss += __shfl_xor_sync(0xffffffffu, ss, o);

    __shared__ float wsum[16];
    if ((tid & 31) == 0) wsum[tid >> 5] = ss;
    __syncthreads();
    int gid = tid >> 6;
    float tot = wsum[gid * 2] + wsum[gid * 2 + 1];
    float rs = rsqrtf(tot * (1.0f / GRPSZ) + 1e-5f);

    const float* gr = g_proj + (size_t)row * PROJ;
    __half2* yo = (__half2*)(g_a16 + (size_t)row * II);
#pragma unroll
    for (int i = 0; i < 4; i++) {
        int col = tid * 8 + 2 * i;
        float z0 = v[2*i]     * rs * nw[col]     * silu_f(gr[col]);
        float z1 = v[2*i + 1] * rs * nw[col + 1] * silu_f(gr[col + 1]);
        yo[tid * 4 + i] = __floats2half2_rn(z0, z1);
    }
}

// ---------------- launch ----------------
extern "C" void kernel_launch(void* const* d_in, const int* in_sizes, int n_in,
                              void* d_out, int out_size) {
    const float* hs        = (const float*)d_in[0];
    const float* in_proj_w = (const float*)d_in[1];
    const float* conv_w    = (const float*)d_in[2];
    const float* conv_b    = (const float*)d_in[3];
    const float* dt_bias   = (const float*)d_in[4];
    const float* A_log     = (const float*)d_in[5];
    const float* Dv        = (const float*)d_in[6];
    const float* norm_w    = (const float*)d_in[7];
    const float* out_w     = (const float*)d_in[8];

    float* out         = (float*)d_out;
    float* conv_state  = out + OUT_ELEMS;
    float* final_state = conv_state + CS_ELEMS;

    static int inited = 0;
    if (!inited) {
        cudaFuncSetAttribute(gemm_h_kernel,
                             cudaFuncAttributeMaxDynamicSharedMemorySize,
                             GEMM_SMEM_BYTES);
        inited = 1;
    }

    __half* pa16; cudaGetSymbolAddress((void**)&pa16, g_a16);
    __half* pw16; cudaGetSymbolAddress((void**)&pw16, g_w16);
    float* pproj; cudaGetSymbolAddress((void**)&pproj, g_proj);

    // 0. fp32 -> fp16 operands for in_proj GEMM
    {
        int n4 = (BT * DM) / 4;
        tohalf_kernel<<<(n4 + 255) / 256, 256>>>(hs, pa16, n4);
    }
    {
        int n4 = (PROJ * DM) / 4;
        tohalf_kernel<<<(n4 + 255) / 256, 256>>>(in_proj_w, pw16, n4);
    }
    // 1. in_proj GEMM (fp16 tensor cores, 3-stage pipeline)
    {
        dim3 grid((PROJ + 127) / 128, BT / 128);
        gemm_h_kernel<<<grid, 256, GEMM_SMEM_BYTES>>>(pa16, pw16, pproj, BT, PROJ, DM);
    }
    // 2. conv + silu (+ conv_state)
    {
        int total = (BT / 4) * CONVD;
        conv_kernel<<<(total + 255) / 256, 256>>>(conv_w, conv_b, conv_state);
    }
    // 3. dt_p / dA
    {
        int total = BT * HH;
        dt_kernel<<<(total + 255) / 256, 256>>>(dt_bias, A_log);
    }
    // 4. sequential scan (+ final_state)
    scan_kernel<<<BB * HH, 512>>>(Dv, final_state);
    // 5. grouped RMS norm * gate -> fp16 A operand
    norm_kernel<<<BT, 512>>>(norm_w);
    // 6. out_proj weight -> fp16, then out_proj GEMM -> d_out
    {
        int n4 = (DM * II) / 4;
        tohalf_kernel<<<(n4 + 255) / 256, 256>>>(out_w, pw16, n4);
    }
    {
        dim3 grid(DM / 128, BT / 128);
        gemm_h_kernel<<<grid, 256, GEMM_SMEM_BYTES>>>(pa16, pw16, out, BT, DM, II);
    }
}